// round 6
// baseline (speedup 1.0000x reference)
#include <cuda_runtime.h>
#include <math.h>

#define BB    64
#define TT    256
#define WW    20
#define NP    6
#define NT    12
#define CH    32
#define LL1   18
#define LL2   16
#define PROJD 64
#define GATES 256
#define NWIN  (BB*TT)   // 16384

#define ENC_GRID    148
#define ENC_THREADS 512
#define ENC_WARPS   (ENC_THREADS/32)

typedef unsigned long long ull;

// Scratch (device globals per allocation rules)
__device__ float g_xg[NWIN * GATES];   // 16 MB: precomputed input gates
__device__ float g_hs[NWIN * PROJD];   // 4 MB : all LSTM hidden states

// ---- packed f32x2 helpers ---------------------------------------------------
__device__ __forceinline__ ull pk2(float lo, float hi) {
    ull r; asm("mov.b64 %0, {%1, %2};" : "=l"(r) : "f"(lo), "f"(hi)); return r;
}
__device__ __forceinline__ float2 unpk(ull a) {
    float2 v; asm("mov.b64 {%0, %1}, %2;" : "=f"(v.x), "=f"(v.y) : "l"(a)); return v;
}
__device__ __forceinline__ void fma2(ull& d, ull a, ull b) {
    asm("fma.rn.f32x2 %0, %1, %2, %0;" : "+l"(d) : "l"(a), "l"(b));
}
__device__ __forceinline__ ull add2(ull a, ull b) {
    ull r; asm("add.rn.f32x2 %0, %1, %2;" : "=l"(r) : "l"(a), "l"(b)); return r;
}

// ---- HW tanh-based activations (1 MUFU each) -------------------------------
__device__ __forceinline__ float tanhx(float x) {
    float y; asm("tanh.approx.f32 %0, %1;" : "=f"(y) : "f"(x)); return y;
}
__device__ __forceinline__ float sig_t(float x) {
    return fmaf(tanhx(0.5f * x), 0.5f, 0.5f);
}

// ---- shared memory layout (floats) -----------------------------------------
#define S_W1P   0                         // 576
#define S_W2P   (S_W1P + 576)             // 3072
#define S_W1T   (S_W2P + 3072)            // 1152
#define S_W2T   (S_W1T + 1152)            // 3072
#define S_PRWP  (S_W2T + 3072)            // [36 kp][64 j][2] = 4608
#define S_WIHP  (S_PRWP + 4608)           // [32 kp][256 g][2] = 16384
#define S_B1P   (S_WIHP + 16384)
#define S_B2P   (S_B1P + 32)
#define S_B1T   (S_B2P + 32)
#define S_B2T   (S_B1T + 32)
#define S_PRB   (S_B2T + 32)              // 64
#define S_BSUM  (S_PRB + 64)              // 256
#define S_FW    (S_BSUM + 256)            // 8
#define S_FB    (S_FW + 8)                // 8
#define S_WARP  (S_FB + 8)

// per-warp buffers (floats)
#define PW_XS    0                        // 6*40 = 240
#define PW_H1    240                      // 16*52 = 832
#define PW_CAT   1072                     // 2 windows x 80
#define PW_FEAT  1232                     // 2 windows x 64
#define PW_SIZE  1360
#define SMEM_FLOATS (S_WARP + ENC_WARPS * PW_SIZE)
#define SMEM_BYTES  (SMEM_FLOATS * 4)

// ---------------------------------------------------------------------------
// Encoder pass, f32x2 paired over input channels. Warp = one window.
// ---------------------------------------------------------------------------
template<int ICP>
__device__ __forceinline__ void encode_f2(
    const float* __restrict__ xs2,
    const ull* __restrict__ w1p, const float* __restrict__ b1s,
    const ull* __restrict__ w2p, const float* __restrict__ b2s,
    float* __restrict__ h12,
    float* __restrict__ outp, int lane)
{
    // conv1 -> relu -> h12
    {
        ull acc[LL1];
        ull binit = pk2(b1s[lane], 0.f);
        #pragma unroll
        for (int p = 0; p < LL1; p++) acc[p] = binit;
        #pragma unroll 2
        for (int icp = 0; icp < ICP; icp++) {
            ull xv[WW];
            const ulonglong2* xp = (const ulonglong2*)(xs2 + icp * 40);
            #pragma unroll
            for (int q = 0; q < 10; q++) { ulonglong2 t = xp[q]; xv[2*q] = t.x; xv[2*q+1] = t.y; }
            const ull* wb_ = w1p + icp * 96;
            ull w0 = wb_[lane], w1 = wb_[32 + lane], w2 = wb_[64 + lane];
            #pragma unroll
            for (int p = 0; p < LL1; p++) {
                fma2(acc[p], xv[p],     w0);
                fma2(acc[p], xv[p + 1], w1);
                fma2(acc[p], xv[p + 2], w2);
            }
        }
        float* dst = h12 + (lane >> 1) * 52 + (lane & 1);
        #pragma unroll
        for (int p = 0; p < LL1; p++) {
            float2 r = unpk(acc[p]);
            dst[2 * p] = fmaxf(r.x + r.y, 0.f);
        }
    }
    __syncwarp();

    // conv2 -> relu -> mean
    {
        ull acc[LL2];
        ull binit = pk2(b2s[lane], 0.f);
        #pragma unroll
        for (int p = 0; p < LL2; p++) acc[p] = binit;
        #pragma unroll 2
        for (int icp = 0; icp < 16; icp++) {
            ull hv[LL1];
            const ulonglong2* hp = (const ulonglong2*)(h12 + icp * 52);
            #pragma unroll
            for (int q = 0; q < 9; q++) { ulonglong2 t = hp[q]; hv[2*q] = t.x; hv[2*q+1] = t.y; }
            const ull* wb_ = w2p + icp * 96;
            ull w0 = wb_[lane], w1 = wb_[32 + lane], w2 = wb_[64 + lane];
            #pragma unroll
            for (int p = 0; p < LL2; p++) {
                fma2(acc[p], hv[p],     w0);
                fma2(acc[p], hv[p + 1], w1);
                fma2(acc[p], hv[p + 2], w2);
            }
        }
        float sum = 0.f;
        #pragma unroll
        for (int p = 0; p < LL2; p++) {
            float2 r = unpk(acc[p]);
            sum += fmaxf(r.x + r.y, 0.f);
        }
        outp[lane] = sum * (1.f / 16.f);
    }
    __syncwarp();
}

// ---------------------------------------------------------------------------
__global__ __launch_bounds__(ENC_THREADS, 1) void encode_kernel(
    const float* __restrict__ pressure, const float* __restrict__ torque,
    const float* __restrict__ frag,
    const float* __restrict__ pw1, const float* __restrict__ pb1,
    const float* __restrict__ pw2, const float* __restrict__ pb2,
    const float* __restrict__ tw1, const float* __restrict__ tb1,
    const float* __restrict__ tw2, const float* __restrict__ tb2,
    const float* __restrict__ fw,  const float* __restrict__ fb,
    const float* __restrict__ prw, const float* __restrict__ prb,
    const float* __restrict__ Wih, const float* __restrict__ bih,
    const float* __restrict__ bhh)
{
    extern __shared__ __align__(16) float sm[];
    const int tid = threadIdx.x;
    const int warp = tid >> 5, lane = tid & 31;

    // ---- stage paired weights into smem ----
    for (int i = tid; i < 576; i += ENC_THREADS) {
        int half = i & 1, j = i >> 1, ln = j & 31, q = j >> 5;
        int t = q % 3, icp = q / 3, ic = 2 * icp + half;
        sm[S_W1P + i] = pw1[ln * (NP * 3) + ic * 3 + t];
    }
    for (int i = tid; i < 3072; i += ENC_THREADS) {
        int half = i & 1, j = i >> 1, ln = j & 31, q = j >> 5;
        int t = q % 3, icp = q / 3, ic = 2 * icp + half;
        sm[S_W2P + i] = pw2[ln * (CH * 3) + ic * 3 + t];
    }
    for (int i = tid; i < 1152; i += ENC_THREADS) {
        int half = i & 1, j = i >> 1, ln = j & 31, q = j >> 5;
        int t = q % 3, icp = q / 3, ic = 2 * icp + half;
        sm[S_W1T + i] = tw1[ln * (NT * 3) + ic * 3 + t];
    }
    for (int i = tid; i < 3072; i += ENC_THREADS) {
        int half = i & 1, j = i >> 1, ln = j & 31, q = j >> 5;
        int t = q % 3, icp = q / 3, ic = 2 * icp + half;
        sm[S_W2T + i] = tw2[ln * (CH * 3) + ic * 3 + t];
    }
    for (int i = tid; i < 4608; i += ENC_THREADS) {
        int half = i & 1, j = i >> 1, jc = j & 63, kp = j >> 6;
        sm[S_PRWP + i] = prw[jc * 72 + 2 * kp + half];
    }
    for (int i = tid; i < 16384; i += ENC_THREADS) {
        int half = i & 1, j = i >> 1, g = j & 255, kp = j >> 8;
        sm[S_WIHP + i] = Wih[g * 64 + 2 * kp + half];
    }
    if (tid < 32) {
        sm[S_B1P + tid] = pb1[tid];
        sm[S_B2P + tid] = pb2[tid];
        sm[S_B1T + tid] = tb1[tid];
        sm[S_B2T + tid] = tb2[tid];
    }
    if (tid < 64) sm[S_PRB + tid] = prb[tid];
    if (tid < GATES) sm[S_BSUM + tid] = bih[tid] + bhh[tid];
    if (tid < 8) { sm[S_FW + tid] = fw[tid]; sm[S_FB + tid] = fb[tid]; }
    __syncthreads();

    float* wb    = sm + S_WARP + warp * PW_SIZE;
    float* xs2   = wb + PW_XS;
    float* h12   = wb + PW_H1;
    float* cat0  = wb + PW_CAT;
    float* cat1  = wb + PW_CAT + 80;
    float* feat0 = wb + PW_FEAT;
    float* feat1 = wb + PW_FEAT + 64;

    // hoisted staging index tables
    int dp[4], dt[8];
    #pragma unroll
    for (int k = 0; k < 4; k++) {
        int i = lane + 32 * k;
        if (i < WW * NP) { int l = i / NP, c = i % NP; dp[k] = (c >> 1) * 40 + 2 * l + (c & 1); }
        else dp[k] = -1;
    }
    #pragma unroll
    for (int k = 0; k < 8; k++) {
        int i = lane + 32 * k;
        if (i < WW * NT) { int l = i / NT, c = i % NT; dt[k] = (c >> 1) * 40 + 2 * l + (c & 1); }
        else dt[k] = -1;
    }

    const ull* w1pp = (const ull*)(sm + S_W1P);
    const ull* w2pp = (const ull*)(sm + S_W2P);
    const ull* w1tp = (const ull*)(sm + S_W1T);
    const ull* w2tp = (const ull*)(sm + S_W2T);

    const int gwarp = blockIdx.x * ENC_WARPS + warp;
    const int stride2 = ENC_GRID * ENC_WARPS * 2;

    for (int base = gwarp * 2; base < NWIN; base += stride2) {
        const int b = base / TT;   // pair never crosses a batch row (base even)

        // ---- conv encoders for the two windows ----
        #pragma unroll 1
        for (int w = 0; w < 2; w++) {
            const int n = base + w;
            float* cats = (w == 0) ? cat0 : cat1;
            {
                const float* src = pressure + (size_t)n * (WW * NP);
                #pragma unroll
                for (int k = 0; k < 4; k++)
                    if (dp[k] >= 0) xs2[dp[k]] = src[lane + 32 * k];
            }
            __syncwarp();
            encode_f2<NP/2>(xs2, w1pp, sm + S_B1P, w2pp, sm + S_B2P, h12, cats, lane);
            {
                const float* src = torque + (size_t)n * (WW * NT);
                #pragma unroll
                for (int k = 0; k < 8; k++)
                    if (dt[k] >= 0) xs2[dt[k]] = src[lane + 32 * k];
            }
            __syncwarp();
            encode_f2<NT/2>(xs2, w1tp, sm + S_B1T, w2tp, sm + S_B2T, h12, cats + CH, lane);
            if (lane < 8) {
                float fv = __ldg(frag + b);
                cats[2 * CH + lane] = fmaxf(fv * sm[S_FW + lane] + sm[S_FB + lane], 0.f);
            }
            __syncwarp();
        }

        // ---- projection 72 -> 64 (relu) for both windows, shared weight LDS ----
        {
            ull a00 = pk2(sm[S_PRB + lane], 0.f);
            ull a01 = pk2(sm[S_PRB + lane + 32], 0.f);
            ull a10 = a00, a11 = a01;
            const ull* c0 = (const ull*)cat0;
            const ull* c1 = (const ull*)cat1;
            const ull* pp = (const ull*)(sm + S_PRWP);
            #pragma unroll 6
            for (int kp = 0; kp < 36; kp++) {
                ull w0 = pp[kp * 64 + lane];
                ull w1 = pp[kp * 64 + lane + 32];
                ull cv0 = c0[kp], cv1 = c1[kp];
                fma2(a00, cv0, w0); fma2(a01, cv0, w1);
                fma2(a10, cv1, w0); fma2(a11, cv1, w1);
            }
            float2 r;
            r = unpk(a00); feat0[lane]      = fmaxf(r.x + r.y, 0.f);
            r = unpk(a01); feat0[lane + 32] = fmaxf(r.x + r.y, 0.f);
            r = unpk(a10); feat1[lane]      = fmaxf(r.x + r.y, 0.f);
            r = unpk(a11); feat1[lane + 32] = fmaxf(r.x + r.y, 0.f);
        }
        __syncwarp();

        // ---- xg for both windows, shared weight LDS ----
        {
            ull acc0[8], acc1[8];
            #pragma unroll
            for (int u = 0; u < 8; u++) {
                ull bi = pk2(sm[S_BSUM + lane + 32 * u], 0.f);
                acc0[u] = bi; acc1[u] = bi;
            }
            const ull* f0 = (const ull*)feat0;
            const ull* f1 = (const ull*)feat1;
            const ull* wp = (const ull*)(sm + S_WIHP);
            #pragma unroll 2
            for (int kp = 0; kp < 32; kp++) {
                ull fv0 = f0[kp], fv1 = f1[kp];
                #pragma unroll
                for (int u = 0; u < 8; u++) {
                    ull wv = wp[kp * 256 + lane + 32 * u];
                    fma2(acc0[u], fv0, wv);
                    fma2(acc1[u], fv1, wv);
                }
            }
            float* xg0 = g_xg + (size_t)base * GATES;
            float* xg1 = xg0 + GATES;
            #pragma unroll
            for (int u = 0; u < 8; u++) {
                float2 r0 = unpk(acc0[u]);
                float2 r1 = unpk(acc1[u]);
                xg0[lane + 32 * u] = r0.x + r0.y;
                xg1[lane + 32 * u] = r1.x + r1.y;
            }
        }
        __syncwarp();
    }
}

// ---------------------------------------------------------------------------
// LSTM: block = batch row, 256 threads. Lane group of 4 = one hidden unit's
// 4 gates (i,f,g,o). Shuffle gate exchange, tanh.approx activations,
// double-buffered h, ONE barrier per step.
// ---------------------------------------------------------------------------
__global__ __launch_bounds__(256) void lstm_kernel(
    const float* __restrict__ Whh, float* __restrict__ out_tail)
{
    const int b = blockIdx.x;
    const int t = threadIdx.x;
    const int w = t >> 5, l = t & 31;
    const int j = w * 8 + (l >> 2);   // hidden unit
    const int q = l & 3;              // gate: 0=i 1=f 2=g 3=o
    const int r = q * PROJD + j;      // row in Whh / xg

    __shared__ __align__(16) float h_s[2][PROJD];

    ull whh2[32];
    const ulonglong2* wr = (const ulonglong2*)(Whh + r * PROJD);
    #pragma unroll
    for (int k = 0; k < 16; k++) {
        ulonglong2 tt = wr[k];
        whh2[2 * k] = tt.x; whh2[2 * k + 1] = tt.y;
    }
    if (q == 0) h_s[0][j] = 0.f;
    float c = 0.f;
    float hn = 0.f;

    const float* xgb = g_xg + (size_t)b * TT * GATES + r;
    float xn0 = xgb[0];
    float xn1 = xgb[GATES];
    float* hso = g_hs + (size_t)b * TT * PROJD;
    __syncthreads();

    for (int ts = 0; ts < TT; ts++) {
        float xcur = xn0;
        xn0 = xn1;
        if (ts + 2 < TT) xn1 = xgb[(size_t)(ts + 2) * GATES];

        ull a0 = pk2(xcur, 0.f), a1 = pk2(0.f, 0.f);
        ull a2 = pk2(0.f, 0.f),  a3 = pk2(0.f, 0.f);
        const ulonglong2* hp = (const ulonglong2*)h_s[ts & 1];
        #pragma unroll
        for (int k = 0; k < 8; k++) {
            ulonglong2 h01 = hp[2 * k], h23 = hp[2 * k + 1];
            fma2(a0, h01.x, whh2[4 * k]);
            fma2(a1, h01.y, whh2[4 * k + 1]);
            fma2(a2, h23.x, whh2[4 * k + 2]);
            fma2(a3, h23.y, whh2[4 * k + 3]);
        }
        float2 rr = unpk(add2(add2(a0, a1), add2(a2, a3)));
        float gv = rr.x + rr.y;

        const int gbase = l & ~3;
        float iv  = __shfl_sync(0xffffffffu, gv, gbase + 0);
        float fvv = __shfl_sync(0xffffffffu, gv, gbase + 1);
        float gg  = __shfl_sync(0xffffffffu, gv, gbase + 2);
        float ov  = __shfl_sync(0xffffffffu, gv, gbase + 3);

        c = sig_t(fvv) * c + sig_t(iv) * tanhx(gg);
        hn = sig_t(ov) * tanhx(c);
        if (q == 0) {
            h_s[(ts + 1) & 1][j] = hn;
            hso[ts * PROJD + j] = hn;
        }
        __syncthreads();
    }
    if (q == 0) {
        out_tail[NWIN * 4 + b * PROJD + j] = hn;                  // hT
        out_tail[NWIN * 4 + BB * PROJD + b * PROJD + j] = c;      // cT
    }
}

// ---------------------------------------------------------------------------
// Head: out[n,k] = sigmoid(h[n] . hw[k] + hb[k])
// ---------------------------------------------------------------------------
__global__ __launch_bounds__(256) void head_kernel(
    const float* __restrict__ hw, const float* __restrict__ hb,
    float* __restrict__ out)
{
    int idx = blockIdx.x * blockDim.x + threadIdx.x;
    if (idx >= NWIN * 4) return;
    int k = idx & 3;
    int n = idx >> 2;
    const ulonglong2* hp = (const ulonglong2*)(g_hs + (size_t)n * PROJD);
    const ulonglong2* wp = (const ulonglong2*)(hw + k * PROJD);
    ull a0 = pk2(__ldg(hb + k), 0.f), a1 = pk2(0.f, 0.f);
    #pragma unroll
    for (int qq = 0; qq < 16; qq++) {
        ulonglong2 h = hp[qq];
        ulonglong2 wv = wp[qq];
        fma2(a0, h.x, wv.x);
        fma2(a1, h.y, wv.y);
    }
    float2 r = unpk(add2(a0, a1));
    out[idx] = sig_t(r.x + r.y);
}

// ---------------------------------------------------------------------------
extern "C" void kernel_launch(void* const* d_in, const int* in_sizes, int n_in,
                              void* d_out, int out_size)
{
    const float* pressure = (const float*)d_in[0];
    const float* torque   = (const float*)d_in[1];
    const float* frag     = (const float*)d_in[2];
    const float* pw1 = (const float*)d_in[3];
    const float* pb1 = (const float*)d_in[4];
    const float* pw2 = (const float*)d_in[5];
    const float* pb2 = (const float*)d_in[6];
    const float* tw1 = (const float*)d_in[7];
    const float* tb1 = (const float*)d_in[8];
    const float* tw2 = (const float*)d_in[9];
    const float* tb2 = (const float*)d_in[10];
    const float* fw  = (const float*)d_in[11];
    const float* fb  = (const float*)d_in[12];
    const float* prw = (const float*)d_in[13];
    const float* prb = (const float*)d_in[14];
    const float* Wih = (const float*)d_in[15];
    const float* Whh = (const float*)d_in[16];
    const float* bih = (const float*)d_in[17];
    const float* bhh = (const float*)d_in[18];
    const float* hw  = (const float*)d_in[19];
    const float* hb  = (const float*)d_in[20];
    float* out = (float*)d_out;

    cudaFuncSetAttribute(encode_kernel,
                         cudaFuncAttributeMaxDynamicSharedMemorySize, SMEM_BYTES);

    encode_kernel<<<ENC_GRID, ENC_THREADS, SMEM_BYTES>>>(
        pressure, torque, frag,
        pw1, pb1, pw2, pb2, tw1, tb1, tw2, tb2,
        fw, fb, prw, prb, Wih, bih, bhh);
    lstm_kernel<<<BB, 256>>>(Whh, out);
    head_kernel<<<(NWIN * 4 + 255) / 256, 256>>>(hw, hb, out);
}

// round 10
// speedup vs baseline: 1.0705x; 1.0705x over previous
#include <cuda_runtime.h>
#include <math.h>

#define BB    64
#define TT    256
#define WW    20
#define NP    6
#define NT    12
#define CH    32
#define LL1   18
#define LL2   16
#define PROJD 64
#define GATES 256
#define NWIN  (BB*TT)   // 16384

#define ENC_GRID    148
#define ENC_THREADS 512
#define ENC_WARPS   (ENC_THREADS/32)

typedef unsigned long long ull;

// Scratch (device global per allocation rules)
__device__ float g_xg[NWIN * GATES];   // 16 MB: precomputed input gates

// ---- packed f32x2 helpers ---------------------------------------------------
__device__ __forceinline__ ull pk2(float lo, float hi) {
    ull r; asm("mov.b64 %0, {%1, %2};" : "=l"(r) : "f"(lo), "f"(hi)); return r;
}
__device__ __forceinline__ float2 unpk(ull a) {
    float2 v; asm("mov.b64 {%0, %1}, %2;" : "=f"(v.x), "=f"(v.y) : "l"(a)); return v;
}
__device__ __forceinline__ void fma2(ull& d, ull a, ull b) {
    asm("fma.rn.f32x2 %0, %1, %2, %0;" : "+l"(d) : "l"(a), "l"(b));
}
__device__ __forceinline__ ull add2(ull a, ull b) {
    ull r; asm("add.rn.f32x2 %0, %1, %2;" : "=l"(r) : "l"(a), "l"(b)); return r;
}

// ---- HW tanh-based activations (1 MUFU each) -------------------------------
__device__ __forceinline__ float tanhx(float x) {
    float y; asm("tanh.approx.f32 %0, %1;" : "=f"(y) : "f"(x)); return y;
}
__device__ __forceinline__ float sig_t(float x) {
    return fmaf(tanhx(0.5f * x), 0.5f, 0.5f);
}

// ---- shared memory layout (floats) -----------------------------------------
#define S_W1P   0                         // 576
#define S_W2P   (S_W1P + 576)             // 3072
#define S_W1T   (S_W2P + 3072)            // 1152
#define S_W2T   (S_W1T + 1152)            // 3072
#define S_PRWP  (S_W2T + 3072)            // [36 kp][64 j][2] = 4608
#define S_WIHP  (S_PRWP + 4608)           // [32 kp][256 g][2] = 16384
#define S_B1P   (S_WIHP + 16384)
#define S_B2P   (S_B1P + 32)
#define S_B1T   (S_B2P + 32)
#define S_B2T   (S_B1T + 32)
#define S_PRB   (S_B2T + 32)              // 64
#define S_BSUM  (S_PRB + 64)              // 256
#define S_FW    (S_BSUM + 256)            // 8
#define S_FB    (S_FW + 8)                // 8
#define S_WARP  (S_FB + 8)

// per-warp buffers (floats)
#define PW_XS    0                        // 6*40 = 240
#define PW_H1    240                      // 16*52 = 832
#define PW_CAT   1072                     // 2 windows x 80
#define PW_FEAT  1232                     // 2 windows x 64
#define PW_SIZE  1360
#define SMEM_FLOATS (S_WARP + ENC_WARPS * PW_SIZE)
#define SMEM_BYTES  (SMEM_FLOATS * 4)

// ---------------------------------------------------------------------------
// Encoder pass, f32x2 paired over input channels. Warp = one window.
// ---------------------------------------------------------------------------
template<int ICP>
__device__ __forceinline__ void encode_f2(
    const float* __restrict__ xs2,
    const ull* __restrict__ w1p, const float* __restrict__ b1s,
    const ull* __restrict__ w2p, const float* __restrict__ b2s,
    float* __restrict__ h12,
    float* __restrict__ outp, int lane)
{
    // conv1 -> relu -> h12
    {
        ull acc[LL1];
        ull binit = pk2(b1s[lane], 0.f);
        #pragma unroll
        for (int p = 0; p < LL1; p++) acc[p] = binit;
        #pragma unroll 2
        for (int icp = 0; icp < ICP; icp++) {
            ull xv[WW];
            const ulonglong2* xp = (const ulonglong2*)(xs2 + icp * 40);
            #pragma unroll
            for (int q = 0; q < 10; q++) { ulonglong2 t = xp[q]; xv[2*q] = t.x; xv[2*q+1] = t.y; }
            const ull* wb_ = w1p + icp * 96;
            ull w0 = wb_[lane], w1 = wb_[32 + lane], w2 = wb_[64 + lane];
            #pragma unroll
            for (int p = 0; p < LL1; p++) {
                fma2(acc[p], xv[p],     w0);
                fma2(acc[p], xv[p + 1], w1);
                fma2(acc[p], xv[p + 2], w2);
            }
        }
        float* dst = h12 + (lane >> 1) * 52 + (lane & 1);
        #pragma unroll
        for (int p = 0; p < LL1; p++) {
            float2 r = unpk(acc[p]);
            dst[2 * p] = fmaxf(r.x + r.y, 0.f);
        }
    }
    __syncwarp();

    // conv2 -> relu -> mean
    {
        ull acc[LL2];
        ull binit = pk2(b2s[lane], 0.f);
        #pragma unroll
        for (int p = 0; p < LL2; p++) acc[p] = binit;
        #pragma unroll 2
        for (int icp = 0; icp < 16; icp++) {
            ull hv[LL1];
            const ulonglong2* hp = (const ulonglong2*)(h12 + icp * 52);
            #pragma unroll
            for (int q = 0; q < 9; q++) { ulonglong2 t = hp[q]; hv[2*q] = t.x; hv[2*q+1] = t.y; }
            const ull* wb_ = w2p + icp * 96;
            ull w0 = wb_[lane], w1 = wb_[32 + lane], w2 = wb_[64 + lane];
            #pragma unroll
            for (int p = 0; p < LL2; p++) {
                fma2(acc[p], hv[p],     w0);
                fma2(acc[p], hv[p + 1], w1);
                fma2(acc[p], hv[p + 2], w2);
            }
        }
        float sum = 0.f;
        #pragma unroll
        for (int p = 0; p < LL2; p++) {
            float2 r = unpk(acc[p]);
            sum += fmaxf(r.x + r.y, 0.f);
        }
        outp[lane] = sum * (1.f / 16.f);
    }
    __syncwarp();
}

// ---------------------------------------------------------------------------
__global__ __launch_bounds__(ENC_THREADS, 1) void encode_kernel(
    const float* __restrict__ pressure, const float* __restrict__ torque,
    const float* __restrict__ frag,
    const float* __restrict__ pw1, const float* __restrict__ pb1,
    const float* __restrict__ pw2, const float* __restrict__ pb2,
    const float* __restrict__ tw1, const float* __restrict__ tb1,
    const float* __restrict__ tw2, const float* __restrict__ tb2,
    const float* __restrict__ fw,  const float* __restrict__ fb,
    const float* __restrict__ prw, const float* __restrict__ prb,
    const float* __restrict__ Wih, const float* __restrict__ bih,
    const float* __restrict__ bhh)
{
    extern __shared__ __align__(16) float sm[];
    const int tid = threadIdx.x;
    const int warp = tid >> 5, lane = tid & 31;

    // ---- stage paired weights into smem ----
    for (int i = tid; i < 576; i += ENC_THREADS) {
        int half = i & 1, j = i >> 1, ln = j & 31, q = j >> 5;
        int t = q % 3, icp = q / 3, ic = 2 * icp + half;
        sm[S_W1P + i] = pw1[ln * (NP * 3) + ic * 3 + t];
    }
    for (int i = tid; i < 3072; i += ENC_THREADS) {
        int half = i & 1, j = i >> 1, ln = j & 31, q = j >> 5;
        int t = q % 3, icp = q / 3, ic = 2 * icp + half;
        sm[S_W2P + i] = pw2[ln * (CH * 3) + ic * 3 + t];
    }
    for (int i = tid; i < 1152; i += ENC_THREADS) {
        int half = i & 1, j = i >> 1, ln = j & 31, q = j >> 5;
        int t = q % 3, icp = q / 3, ic = 2 * icp + half;
        sm[S_W1T + i] = tw1[ln * (NT * 3) + ic * 3 + t];
    }
    for (int i = tid; i < 3072; i += ENC_THREADS) {
        int half = i & 1, j = i >> 1, ln = j & 31, q = j >> 5;
        int t = q % 3, icp = q / 3, ic = 2 * icp + half;
        sm[S_W2T + i] = tw2[ln * (CH * 3) + ic * 3 + t];
    }
    for (int i = tid; i < 4608; i += ENC_THREADS) {
        int half = i & 1, j = i >> 1, jc = j & 63, kp = j >> 6;
        sm[S_PRWP + i] = prw[jc * 72 + 2 * kp + half];
    }
    for (int i = tid; i < 16384; i += ENC_THREADS) {
        int half = i & 1, j = i >> 1, g = j & 255, kp = j >> 8;
        sm[S_WIHP + i] = Wih[g * 64 + 2 * kp + half];
    }
    if (tid < 32) {
        sm[S_B1P + tid] = pb1[tid];
        sm[S_B2P + tid] = pb2[tid];
        sm[S_B1T + tid] = tb1[tid];
        sm[S_B2T + tid] = tb2[tid];
    }
    if (tid < 64) sm[S_PRB + tid] = prb[tid];
    if (tid < GATES) sm[S_BSUM + tid] = bih[tid] + bhh[tid];
    if (tid < 8) { sm[S_FW + tid] = fw[tid]; sm[S_FB + tid] = fb[tid]; }
    __syncthreads();

    float* wb    = sm + S_WARP + warp * PW_SIZE;
    float* xs2   = wb + PW_XS;
    float* h12   = wb + PW_H1;
    float* cat0  = wb + PW_CAT;
    float* cat1  = wb + PW_CAT + 80;
    float* feat0 = wb + PW_FEAT;
    float* feat1 = wb + PW_FEAT + 64;

    // hoisted staging index tables
    int dp[4], dt[8];
    #pragma unroll
    for (int k = 0; k < 4; k++) {
        int i = lane + 32 * k;
        if (i < WW * NP) { int l = i / NP, c = i % NP; dp[k] = (c >> 1) * 40 + 2 * l + (c & 1); }
        else dp[k] = -1;
    }
    #pragma unroll
    for (int k = 0; k < 8; k++) {
        int i = lane + 32 * k;
        if (i < WW * NT) { int l = i / NT, c = i % NT; dt[k] = (c >> 1) * 40 + 2 * l + (c & 1); }
        else dt[k] = -1;
    }

    const ull* w1pp = (const ull*)(sm + S_W1P);
    const ull* w2pp = (const ull*)(sm + S_W2P);
    const ull* w1tp = (const ull*)(sm + S_W1T);
    const ull* w2tp = (const ull*)(sm + S_W2T);

    const int gwarp = blockIdx.x * ENC_WARPS + warp;
    const int stride2 = ENC_GRID * ENC_WARPS * 2;

    for (int base = gwarp * 2; base < NWIN; base += stride2) {
        const int b = base / TT;   // pair never crosses a batch row (base even)

        // ---- L2 prefetch of NEXT pair's inputs (hides DRAM latency) ----
        {
            int nn = base + stride2;
            if (nn >= NWIN) nn = base;
            const float* pn = pressure + (size_t)nn * (WW * NP);
            const float* tn = torque + (size_t)nn * (WW * NT);
            if (lane < 8)
                asm volatile("prefetch.global.L2 [%0];" :: "l"(pn + lane * 34));
            if (lane < 15)
                asm volatile("prefetch.global.L2 [%0];" :: "l"(tn + lane * 32));
        }

        // ---- conv encoders for the two windows ----
        #pragma unroll 1
        for (int w = 0; w < 2; w++) {
            const int n = base + w;
            float* cats = (w == 0) ? cat0 : cat1;
            {
                const float* src = pressure + (size_t)n * (WW * NP);
                #pragma unroll
                for (int k = 0; k < 4; k++)
                    if (dp[k] >= 0) xs2[dp[k]] = src[lane + 32 * k];
            }
            __syncwarp();
            encode_f2<NP/2>(xs2, w1pp, sm + S_B1P, w2pp, sm + S_B2P, h12, cats, lane);
            {
                const float* src = torque + (size_t)n * (WW * NT);
                #pragma unroll
                for (int k = 0; k < 8; k++)
                    if (dt[k] >= 0) xs2[dt[k]] = src[lane + 32 * k];
            }
            __syncwarp();
            encode_f2<NT/2>(xs2, w1tp, sm + S_B1T, w2tp, sm + S_B2T, h12, cats + CH, lane);
            if (lane < 8) {
                float fv = __ldg(frag + b);
                cats[2 * CH + lane] = fmaxf(fv * sm[S_FW + lane] + sm[S_FB + lane], 0.f);
            }
            __syncwarp();
        }

        // ---- projection 72 -> 64 (relu) for both windows, shared weight LDS ----
        {
            ull a00 = pk2(sm[S_PRB + lane], 0.f);
            ull a01 = pk2(sm[S_PRB + lane + 32], 0.f);
            ull a10 = a00, a11 = a01;
            const ull* c0 = (const ull*)cat0;
            const ull* c1 = (const ull*)cat1;
            const ull* pp = (const ull*)(sm + S_PRWP);
            #pragma unroll 6
            for (int kp = 0; kp < 36; kp++) {
                ull w0 = pp[kp * 64 + lane];
                ull w1 = pp[kp * 64 + lane + 32];
                ull cv0 = c0[kp], cv1 = c1[kp];
                fma2(a00, cv0, w0); fma2(a01, cv0, w1);
                fma2(a10, cv1, w0); fma2(a11, cv1, w1);
            }
            float2 r;
            r = unpk(a00); feat0[lane]      = fmaxf(r.x + r.y, 0.f);
            r = unpk(a01); feat0[lane + 32] = fmaxf(r.x + r.y, 0.f);
            r = unpk(a10); feat1[lane]      = fmaxf(r.x + r.y, 0.f);
            r = unpk(a11); feat1[lane + 32] = fmaxf(r.x + r.y, 0.f);
        }
        __syncwarp();

        // ---- xg for both windows, shared weight LDS ----
        {
            ull acc0[8], acc1[8];
            #pragma unroll
            for (int u = 0; u < 8; u++) {
                ull bi = pk2(sm[S_BSUM + lane + 32 * u], 0.f);
                acc0[u] = bi; acc1[u] = bi;
            }
            const ull* f0 = (const ull*)feat0;
            const ull* f1 = (const ull*)feat1;
            const ull* wp = (const ull*)(sm + S_WIHP);
            #pragma unroll 2
            for (int kp = 0; kp < 32; kp++) {
                ull fv0 = f0[kp], fv1 = f1[kp];
                #pragma unroll
                for (int u = 0; u < 8; u++) {
                    ull wv = wp[kp * 256 + lane + 32 * u];
                    fma2(acc0[u], fv0, wv);
                    fma2(acc1[u], fv1, wv);
                }
            }
            float* xg0 = g_xg + (size_t)base * GATES;
            float* xg1 = xg0 + GATES;
            #pragma unroll
            for (int u = 0; u < 8; u++) {
                float2 r0 = unpk(acc0[u]);
                float2 r1 = unpk(acc1[u]);
                xg0[lane + 32 * u] = r0.x + r0.y;
                xg1[lane + 32 * u] = r1.x + r1.y;
            }
        }
        __syncwarp();
    }
}

// ---------------------------------------------------------------------------
// LSTM + fused head. Block = batch row, thread = gate (0..255).
// g_sh exchange, double-buffered h. During the act phase (warps 2-7 idle),
// warp 2 computes the head output for step ts-1 from the stable h buffer.
// ---------------------------------------------------------------------------
__global__ __launch_bounds__(256) void lstm_kernel(
    const float* __restrict__ Whh, const float* __restrict__ hw,
    const float* __restrict__ hb, float* __restrict__ out)
{
    const int b = blockIdx.x;
    const int g = threadIdx.x;
    const int w = g >> 5, l = g & 31;

    __shared__ __align__(16) float h_s[2][PROJD];
    __shared__ float g_sh[GATES];

    ull whh2[32];
    const ulonglong2* wr = (const ulonglong2*)(Whh + g * PROJD);
    #pragma unroll
    for (int k = 0; k < 16; k++) {
        ulonglong2 t = wr[k];
        whh2[2 * k] = t.x; whh2[2 * k + 1] = t.y;
    }

    // head weights (warp 2 only): lane l -> output hk, partial-range hi
    const int hk = l >> 3, hi = l & 7;
    float hwreg[8]; float hbk = 0.f;
    if (w == 2) {
        #pragma unroll
        for (int qq = 0; qq < 8; qq++) hwreg[qq] = __ldg(hw + hk * PROJD + hi * 8 + qq);
        hbk = __ldg(hb + hk);
    }

    if (g < PROJD) h_s[0][g] = 0.f;
    float c = 0.f, hn = 0.f;
    __syncthreads();

    const float* xgb = g_xg + (size_t)b * TT * GATES + g;
    float xn0 = xgb[0];
    float xn1 = xgb[GATES];
    float* outb = out + (size_t)b * TT * 4;

    for (int ts = 0; ts < TT; ts++) {
        ull a0 = pk2(xn0, 0.f), a1 = pk2(0.f, 0.f);
        ull a2 = pk2(0.f, 0.f),  a3 = pk2(0.f, 0.f);
        xn0 = xn1;
        if (ts + 2 < TT) xn1 = xgb[(size_t)(ts + 2) * GATES];
        const ulonglong2* hp = (const ulonglong2*)h_s[ts & 1];
        #pragma unroll
        for (int k = 0; k < 8; k++) {
            ulonglong2 h01 = hp[2 * k], h23 = hp[2 * k + 1];
            fma2(a0, h01.x, whh2[4 * k]);
            fma2(a1, h01.y, whh2[4 * k + 1]);
            fma2(a2, h23.x, whh2[4 * k + 2]);
            fma2(a3, h23.y, whh2[4 * k + 3]);
        }
        float2 r = unpk(add2(add2(a0, a1), add2(a2, a3)));
        g_sh[g] = r.x + r.y;
        __syncthreads();
        if (g < PROJD) {
            float iv = g_sh[g], fv = g_sh[g + 64], gg = g_sh[g + 128], ov = g_sh[g + 192];
            c = sig_t(fv) * c + sig_t(iv) * tanhx(gg);
            hn = sig_t(ov) * tanhx(c);
            h_s[(ts + 1) & 1][g] = hn;       // write NEXT buffer
        } else if (w == 2 && ts > 0) {
            // head for step ts-1 from h_s[ts&1] (stable: act writes other buffer)
            const float* hprev = h_s[ts & 1];
            float s = 0.f;
            #pragma unroll
            for (int qq = 0; qq < 8; qq++) s += hprev[hi * 8 + qq] * hwreg[qq];
            s += __shfl_xor_sync(0xffffffffu, s, 1);
            s += __shfl_xor_sync(0xffffffffu, s, 2);
            s += __shfl_xor_sync(0xffffffffu, s, 4);
            if (hi == 0) outb[(ts - 1) * 4 + hk] = sig_t(s + hbk);
        }
        __syncthreads();
    }
    // head for final step ts = TT-1 (h in h_s[TT&1] == h_s[0])
    if (w == 2) {
        const float* hprev = h_s[TT & 1];
        float s = 0.f;
        #pragma unroll
        for (int qq = 0; qq < 8; qq++) s += hprev[hi * 8 + qq] * hwreg[qq];
        s += __shfl_xor_sync(0xffffffffu, s, 1);
        s += __shfl_xor_sync(0xffffffffu, s, 2);
        s += __shfl_xor_sync(0xffffffffu, s, 4);
        if (hi == 0) outb[(TT - 1) * 4 + hk] = sig_t(s + hbk);
    }
    if (g < PROJD) {
        out[NWIN * 4 + b * PROJD + g] = hn;                  // hT
        out[NWIN * 4 + BB * PROJD + b * PROJD + g] = c;      // cT
    }
}

// ---------------------------------------------------------------------------
extern "C" void kernel_launch(void* const* d_in, const int* in_sizes, int n_in,
                              void* d_out, int out_size)
{
    const float* pressure = (const float*)d_in[0];
    const float* torque   = (const float*)d_in[1];
    const float* frag     = (const float*)d_in[2];
    const float* pw1 = (const float*)d_in[3];
    const float* pb1 = (const float*)d_in[4];
    const float* pw2 = (const float*)d_in[5];
    const float* pb2 = (const float*)d_in[6];
    const float* tw1 = (const float*)d_in[7];
    const float* tb1 = (const float*)d_in[8];
    const float* tw2 = (const float*)d_in[9];
    const float* tb2 = (const float*)d_in[10];
    const float* fw  = (const float*)d_in[11];
    const float* fb  = (const float*)d_in[12];
    const float* prw = (const float*)d_in[13];
    const float* prb = (const float*)d_in[14];
    const float* Wih = (const float*)d_in[15];
    const float* Whh = (const float*)d_in[16];
    const float* bih = (const float*)d_in[17];
    const float* bhh = (const float*)d_in[18];
    const float* hw  = (const float*)d_in[19];
    const float* hb  = (const float*)d_in[20];
    float* out = (float*)d_out;

    cudaFuncSetAttribute(encode_kernel,
                         cudaFuncAttributeMaxDynamicSharedMemorySize, SMEM_BYTES);

    encode_kernel<<<ENC_GRID, ENC_THREADS, SMEM_BYTES>>>(
        pressure, torque, frag,
        pw1, pb1, pw2, pb2, tw1, tb1, tw2, tb2,
        fw, fb, prw, prb, Wih, bih, bhh);
    lstm_kernel<<<BB, 256>>>(Whh, hw, hb, out);
}